// round 12
// baseline (speedup 1.0000x reference)
#include <cuda_runtime.h>

#define N_   4
#define C_   64
#define V_   25
#define T_   300
#define M_   2
#define H_   8
#define HD_  32
#define E_   256
#define B_   8          // N_*M_
#define NTOK 60000      // B_*V_*T_
#define QKVW 768
#define NGRP 1600       // B_*V_*H_
#define GCHUNK 200      // groups per scores/attn chunk
#define NCHUNK 8

typedef unsigned long long u64;

// ---- packed f32x2 helpers (Blackwell FFMA2 path) --------------------------
__device__ __forceinline__ void ffma2(u64& d, u64 a, u64 b) {
    asm("fma.rn.f32x2 %0, %1, %2, %0;" : "+l"(d) : "l"(a), "l"(b));
}
__device__ __forceinline__ u64 fmul2(u64 a, u64 b) {
    u64 r; asm("mul.rn.f32x2 %0, %1, %2;" : "=l"(r) : "l"(a), "l"(b)); return r;
}
__device__ __forceinline__ u64 pack2(float lo, float hi) {
    u64 r; asm("mov.b64 %0, {%1, %2};" : "=l"(r) : "f"(lo), "f"(hi)); return r;
}
__device__ __forceinline__ float2 unpack2(u64 a) {
    float lo, hi; asm("mov.b64 {%0, %1}, %2;" : "=f"(lo), "=f"(hi) : "l"(a));
    return make_float2(lo, hi);
}
__device__ __forceinline__ float hsum2(u64 a) {
    float2 f = unpack2(a); return f.x + f.y;
}

// Scratch (allocation-free: device globals)
__device__ float g_xp[NTOK * C_];                     // packed tokens [60000][64]
__device__ float g_qkv[(size_t)NTOK * QKVW];          // [60000][768] = q|k|v
__device__ float g_ao[(size_t)NTOK * E_];             // attention out [60000][256]
__device__ float g_s[(size_t)GCHUNK * T_ * T_];       // scores window [gl][r][l] (72MB)

// ---------------------------------------------------------------------------
// Kernel 1: pack x (N,C,V,T,M) -> xp [tok][C]
// ---------------------------------------------------------------------------
__global__ void pack_kernel(const float* __restrict__ x) {
    int i = blockIdx.x * 256 + threadIdx.x;   // exactly 3,840,000 threads
    int m = i & 1;
    int t = (i >> 1) % 300;
    int r = i / 600;
    int v = r % 25; r /= 25;
    int c = r & 63;
    int n = r >> 6;
    int tok = (((n * 2 + m) * 25 + v) * 300 + t);
    g_xp[tok * 64 + c] = x[i];
}

// ---------------------------------------------------------------------------
// Kernel 2: QKV GEMM  [60000x64] @ [64x768] + b  -> g_qkv  (FFMA2 mainloop)
// ---------------------------------------------------------------------------
__global__ __launch_bounds__(256) void qkv_gemm(const float* __restrict__ w,
                                                const float* __restrict__ bias) {
    __shared__ __align__(16) float As[64][65];
    __shared__ __align__(16) float Bs[64][64];
    int m0 = blockIdx.x * 64;
    int n0 = blockIdx.y * 64;
    int tid = threadIdx.x;
    int tx = tid & 15, ty = tid >> 4;

#pragma unroll
    for (int it = 0; it < 4; ++it) {
        int lin = tid + it * 256;           // float4 index, 0..1023
        int row = lin >> 4;
        int c4  = (lin & 15) * 4;
        float4 f = make_float4(0.f, 0.f, 0.f, 0.f);
        if (m0 + row < NTOK)
            f = *(const float4*)(g_xp + (size_t)(m0 + row) * 64 + c4);
        As[row][c4 + 0] = f.x; As[row][c4 + 1] = f.y;
        As[row][c4 + 2] = f.z; As[row][c4 + 3] = f.w;
        *(float4*)&Bs[row][c4] = *(const float4*)(w + row * QKVW + n0 + c4);
    }
    __syncthreads();

    float4 bb = *(const float4*)(bias + n0 + tx * 4);
    u64 acc[4][2];
#pragma unroll
    for (int i = 0; i < 4; ++i) {
        acc[i][0] = pack2(bb.x, bb.y);
        acc[i][1] = pack2(bb.z, bb.w);
    }
#pragma unroll
    for (int c = 0; c < 64; ++c) {
        u64 p0 = pack2(As[ty * 4 + 0][c], As[ty * 4 + 0][c]);
        u64 p1 = pack2(As[ty * 4 + 1][c], As[ty * 4 + 1][c]);
        u64 p2 = pack2(As[ty * 4 + 2][c], As[ty * 4 + 2][c]);
        u64 p3 = pack2(As[ty * 4 + 3][c], As[ty * 4 + 3][c]);
        ulonglong2 b2 = *(const ulonglong2*)&Bs[c][tx * 4];
        ffma2(acc[0][0], p0, b2.x); ffma2(acc[0][1], p0, b2.y);
        ffma2(acc[1][0], p1, b2.x); ffma2(acc[1][1], p1, b2.y);
        ffma2(acc[2][0], p2, b2.x); ffma2(acc[2][1], p2, b2.y);
        ffma2(acc[3][0], p3, b2.x); ffma2(acc[3][1], p3, b2.y);
    }
#pragma unroll
    for (int i = 0; i < 4; ++i) {
        int row = m0 + ty * 4 + i;
        if (row < NTOK) {
            float2 lo = unpack2(acc[i][0]);
            float2 hi = unpack2(acc[i][1]);
            float4 f = make_float4(lo.x, lo.y, hi.x, hi.y);
            *(float4*)(g_qkv + (size_t)row * QKVW + n0 + tx * 4) = f;
        }
    }
}

// ---------------------------------------------------------------------------
// Kernel 3: scores. S[gl][r][l] = scale*(q_l . k_r) + q_l . bias[l-r+299]
// 64x64 (l x r) tile per block, 128 threads (8 ty x 16 tx), 8x4 microtile.
// Quad rotation (c + (row>>2)) & 7 -> conflict-free K/bias LDS.128.
// ---------------------------------------------------------------------------
__global__ __launch_bounds__(128, 3) void scores_kernel(const float* __restrict__ bias_table,
                                                        int g0) {
    __shared__ __align__(16) float Qs[64][36];
    __shared__ __align__(16) float Ks[64][36];
    __shared__ __align__(16) float Bs[127][36];

    int gl = blockIdx.x;          // 0..GCHUNK-1
    int g  = g0 + gl;
    int bv = g >> 3;
    int h  = g & 7;
    int l0 = blockIdx.y * 64;
    int r0 = blockIdx.z * 64;
    int tid = threadIdx.x;
    const float* qkv_bv = g_qkv + (size_t)bv * (T_ * QKVW);

    // stage Q (linear) and K (pre-scaled, quad-rotated)
    for (int i = tid; i < 512; i += 128) {          // 64 rows x 8 float4
        int row = i >> 3;
        int c = i & 7;                               // chunk index
        int lq = min(l0 + row, T_ - 1);
        int rq = min(r0 + row, T_ - 1);
        float4 qf = *(const float4*)(qkv_bv + (size_t)lq * QKVW + h * 32 + c * 4);
        *(float4*)&Qs[row][c * 4] = qf;
        float4 kf = *(const float4*)(qkv_bv + (size_t)rq * QKVW + 256 + h * 32 + c * 4);
        kf.x *= 0.0625f; kf.y *= 0.0625f; kf.z *= 0.0625f; kf.w *= 0.0625f;
        *(float4*)&Ks[row][((c + (row >> 2)) & 7) * 4] = kf;
    }
    // stage bias band: rows p = pmin..pmin+126 (clamped), quad-rotated
    int pmin = l0 - r0 + 236;
    for (int i = tid; i < 127 * 8; i += 128) {
        int row = i >> 3;
        int c = i & 7;
        int p = min(max(pmin + row, 0), 2 * T_ - 2);
        *(float4*)&Bs[row][((c + (row >> 2)) & 7) * 4] =
            *(const float4*)(bias_table + p * 32 + c * 4);
    }
    __syncthreads();

    int tx = tid & 15, ty = tid >> 4;    // tx: 16 r-groups of 4, ty: 8 l-groups of 8
    u64 acc[8][4];
#pragma unroll
    for (int i = 0; i < 8; ++i)
#pragma unroll
        for (int j = 0; j < 4; ++j) acc[i][j] = 0ull;

    int bbase = 8 * ty - 4 * tx + 60;    // b2[dd] row = bbase + dd, dd in [0,10]

#pragma unroll
    for (int ch = 0; ch < 8; ++ch) {
        ulonglong2 q2[8], k2[4], b2[11];
#pragma unroll
        for (int i = 0; i < 8; ++i)
            q2[i] = *(const ulonglong2*)&Qs[8 * ty + i][ch * 4];
#pragma unroll
        for (int j = 0; j < 4; ++j)
            k2[j] = *(const ulonglong2*)&Ks[4 * tx + j][((ch + tx) & 7) * 4];
#pragma unroll
        for (int dd = 0; dd < 11; ++dd) {
            int bi = bbase + dd;
            b2[dd] = *(const ulonglong2*)&Bs[bi][((ch + (bi >> 2)) & 7) * 4];
        }
#pragma unroll
        for (int i = 0; i < 8; ++i)
#pragma unroll
            for (int j = 0; j < 4; ++j) {
                ulonglong2 bb = b2[i - j + 3];
                ffma2(acc[i][j], q2[i].x, k2[j].x);
                ffma2(acc[i][j], q2[i].y, k2[j].y);
                ffma2(acc[i][j], q2[i].x, bb.x);
                ffma2(acc[i][j], q2[i].y, bb.y);
            }
    }

    // epilogue: horizontal add, store S[gl][r][l] (l contiguous, float4 pairs)
    int la = l0 + 8 * ty;
#pragma unroll
    for (int j = 0; j < 4; ++j) {
        int r = r0 + 4 * tx + j;
        if (r < T_) {
            float* dst = g_s + ((size_t)gl * T_ + r) * T_ + la;
            if (la + 3 < T_) {
                float4 o = make_float4(hsum2(acc[0][j]), hsum2(acc[1][j]),
                                       hsum2(acc[2][j]), hsum2(acc[3][j]));
                *(float4*)dst = o;
            }
            if (la + 7 < T_) {
                float4 o = make_float4(hsum2(acc[4][j]), hsum2(acc[5][j]),
                                       hsum2(acc[6][j]), hsum2(acc[7][j]));
                *(float4*)(dst + 4) = o;
            }
        }
    }
}

// ---------------------------------------------------------------------------
// Kernel 4: softmax + PV (scores precomputed in g_s window).
// 2 q-blocks of 150 per group, 160 threads, S chunk + V chunk in smem.
// ---------------------------------------------------------------------------
#define QBLK 150
#define NTHR 160
#define KC 60

__global__ __launch_bounds__(NTHR) void attn_kernel(int g0) {
    __shared__ float Ss[KC][QBLK];     // 36000 B, stride-1 per-lane reads
    __shared__ float Vs[KC][32];       // 7680 B, broadcast reads

    int gl = blockIdx.x;          // 0..GCHUNK-1
    int g  = g0 + gl;
    int bv = g >> 3;
    int h  = g & 7;
    int q0 = blockIdx.y * QBLK;   // 0 or 150
    int tid = threadIdx.x;
    const float* qkv_bv = g_qkv + (size_t)bv * (T_ * QKVW);
    const float* srow = g_s + (size_t)gl * (T_ * T_) + q0;

    bool active = (tid < QBLK);
    u64 o2[16];
#pragma unroll
    for (int d = 0; d < 16; ++d) o2[d] = 0ull;
    float mx = -3.0e38f, ssum = 0.f;

    for (int r0 = 0; r0 < T_; r0 += KC) {
        __syncthreads();
        // stage V chunk: 60 rows x 8 float4
        for (int i = tid; i < KC * 8; i += NTHR) {
            int r = i >> 3, d4 = (i & 7) * 4;
            *(float4*)&Vs[r][d4] =
                *(const float4*)(qkv_bv + (size_t)(r0 + r) * QKVW + 512 + h * 32 + d4);
        }
        // stage S chunk: 60 rows x 75 float2
        for (int i = tid; i < KC * 75; i += NTHR) {
            int r = i / 75, c2 = i % 75;
            *(float2*)&Ss[r][c2 * 2] =
                *(const float2*)(srow + (size_t)(r0 + r) * T_ + c2 * 2);
        }
        __syncthreads();
        if (active) {
#pragma unroll 1
            for (int rr = 0; rr < KC; rr += 10) {
                float s[10];
#pragma unroll
                for (int j = 0; j < 10; ++j) s[j] = Ss[rr + j][tid];
                float nm = mx;
#pragma unroll
                for (int j = 0; j < 10; ++j) nm = fmaxf(nm, s[j]);
                float corr = __expf(mx - nm);
                mx = nm;
                ssum *= corr;
                u64 cc = pack2(corr, corr);
#pragma unroll
                for (int d = 0; d < 16; ++d) o2[d] = fmul2(o2[d], cc);
#pragma unroll
                for (int j = 0; j < 10; ++j) {
                    float p = __expf(s[j] - nm);
                    ssum += p;
                    u64 pp = pack2(p, p);
                    const ulonglong2* v2p = (const ulonglong2*)&Vs[rr + j][0];
#pragma unroll
                    for (int i = 0; i < 8; ++i) {
                        ulonglong2 vf = v2p[i];
                        ffma2(o2[2 * i],     pp, vf.x);
                        ffma2(o2[2 * i + 1], pp, vf.y);
                    }
                }
            }
        }
    }

    if (active) {
        float inv = 1.0f / ssum;
        float* op = g_ao + ((size_t)bv * T_ + q0 + tid) * E_ + h * 32;
#pragma unroll
        for (int i = 0; i < 8; ++i) {
            float2 lo = unpack2(o2[2 * i]);
            float2 hi = unpack2(o2[2 * i + 1]);
            float4 f = make_float4(lo.x * inv, lo.y * inv, hi.x * inv, hi.y * inv);
            *(float4*)(op + i * 4) = f;
        }
    }
}

// ---------------------------------------------------------------------------
// Kernel 5: merge GEMM [60000x256]@[256x64] + b, scatter (FFMA2 mainloop)
// ---------------------------------------------------------------------------
__global__ __launch_bounds__(256) void merge_gemm(const float* __restrict__ w,
                                                  const float* __restrict__ bias,
                                                  float* __restrict__ out) {
    __shared__ __align__(16) float As[64][65];
    __shared__ __align__(16) float Bs[64][64];
    int m0 = blockIdx.x * 64;
    int tid = threadIdx.x;
    int tx = tid & 15, ty = tid >> 4;

    float4 bb = *(const float4*)(bias + tx * 4);
    u64 acc[4][2];
#pragma unroll
    for (int i = 0; i < 4; ++i) {
        acc[i][0] = pack2(bb.x, bb.y);
        acc[i][1] = pack2(bb.z, bb.w);
    }

    for (int k0 = 0; k0 < 256; k0 += 64) {
        __syncthreads();
#pragma unroll
        for (int it = 0; it < 4; ++it) {
            int lin = tid + it * 256;
            int row = lin >> 4;
            int c4  = (lin & 15) * 4;
            float4 f = make_float4(0.f, 0.f, 0.f, 0.f);
            if (m0 + row < NTOK)
                f = *(const float4*)(g_ao + (size_t)(m0 + row) * E_ + k0 + c4);
            As[row][c4 + 0] = f.x; As[row][c4 + 1] = f.y;
            As[row][c4 + 2] = f.z; As[row][c4 + 3] = f.w;
            *(float4*)&Bs[row][c4] = *(const float4*)(w + (k0 + row) * 64 + c4);
        }
        __syncthreads();
#pragma unroll
        for (int c = 0; c < 64; ++c) {
            u64 p0 = pack2(As[ty * 4 + 0][c], As[ty * 4 + 0][c]);
            u64 p1 = pack2(As[ty * 4 + 1][c], As[ty * 4 + 1][c]);
            u64 p2 = pack2(As[ty * 4 + 2][c], As[ty * 4 + 2][c]);
            u64 p3 = pack2(As[ty * 4 + 3][c], As[ty * 4 + 3][c]);
            ulonglong2 b2 = *(const ulonglong2*)&Bs[c][tx * 4];
            ffma2(acc[0][0], p0, b2.x); ffma2(acc[0][1], p0, b2.y);
            ffma2(acc[1][0], p1, b2.x); ffma2(acc[1][1], p1, b2.y);
            ffma2(acc[2][0], p2, b2.x); ffma2(acc[2][1], p2, b2.y);
            ffma2(acc[3][0], p3, b2.x); ffma2(acc[3][1], p3, b2.y);
        }
    }

#pragma unroll
    for (int i = 0; i < 4; ++i) {
        int tok = m0 + ty * 4 + i;
        if (tok < NTOK) {
            int t  = tok % 300;
            int bvv = tok / 300;
            int v  = bvv % 25;
            int b  = bvv / 25;
            int n  = b >> 1;
            int mm = b & 1;
            size_t base = (size_t)n * 960000 + (size_t)v * 600 + t * 2 + mm;
            float2 lo = unpack2(acc[i][0]);
            float2 hi = unpack2(acc[i][1]);
            float r[4] = {lo.x, lo.y, hi.x, hi.y};
#pragma unroll
            for (int j = 0; j < 4; ++j)
                out[base + (size_t)(tx * 4 + j) * 15000] = r[j];
        }
    }
}

// ---------------------------------------------------------------------------
extern "C" void kernel_launch(void* const* d_in, const int* in_sizes, int n_in,
                              void* d_out, int out_size) {
    const float* x          = (const float*)d_in[0];
    const float* w_qkv      = (const float*)d_in[1];
    const float* b_qkv      = (const float*)d_in[2];
    const float* w_merge    = (const float*)d_in[3];
    const float* b_merge    = (const float*)d_in[4];
    const float* bias_table = (const float*)d_in[5];
    float* out = (float*)d_out;

    pack_kernel<<<15000, 256>>>(x);

    dim3 g1((NTOK + 63) / 64, QKVW / 64);
    qkv_gemm<<<g1, 256>>>(w_qkv, b_qkv);

    for (int c = 0; c < NCHUNK; ++c) {
        dim3 gs(GCHUNK, 5, 5);         // 200 groups x 5 l-tiles x 5 r-tiles
        scores_kernel<<<gs, 128>>>(bias_table, c * GCHUNK);
        dim3 g2(GCHUNK, 2);            // 200 groups x 2 query blocks of 150
        attn_kernel<<<g2, NTHR>>>(c * GCHUNK);
    }

    merge_gemm<<<(NTOK + 63) / 64, 256>>>(w_merge, b_merge, out);
}

// round 16
// speedup vs baseline: 1.0281x; 1.0281x over previous
#include <cuda_runtime.h>

#define N_   4
#define C_   64
#define V_   25
#define T_   300
#define M_   2
#define H_   8
#define HD_  32
#define E_   256
#define B_   8          // N_*M_
#define NTOK 60000      // B_*V_*T_
#define QKVW 768
#define NGRP 1600       // B_*V_*H_
#define GCHUNK 200      // groups per scores/pv chunk
#define NCHUNK 8

typedef unsigned long long u64;

// ---- packed f32x2 helpers (Blackwell FFMA2 path) --------------------------
__device__ __forceinline__ void ffma2(u64& d, u64 a, u64 b) {
    asm("fma.rn.f32x2 %0, %1, %2, %0;" : "+l"(d) : "l"(a), "l"(b));
}
__device__ __forceinline__ u64 pack2(float lo, float hi) {
    u64 r; asm("mov.b64 %0, {%1, %2};" : "=l"(r) : "f"(lo), "f"(hi)); return r;
}
__device__ __forceinline__ float2 unpack2(u64 a) {
    float lo, hi; asm("mov.b64 {%0, %1}, %2;" : "=f"(lo), "=f"(hi) : "l"(a));
    return make_float2(lo, hi);
}
__device__ __forceinline__ float hsum2(u64 a) {
    float2 f = unpack2(a); return f.x + f.y;
}

// Scratch (allocation-free: device globals)
__device__ float g_xp[NTOK * C_];                     // packed tokens [60000][64]
__device__ float g_qkv[(size_t)NTOK * QKVW];          // [60000][768] = q|k|v
__device__ float g_ao[(size_t)NTOK * E_];             // attention out [60000][256]
__device__ float g_s[(size_t)GCHUNK * T_ * T_];       // scores window [gl][l][r] (72MB)

// ---------------------------------------------------------------------------
// Kernel 1: pack x (N,C,V,T,M) -> xp [tok][C]
// ---------------------------------------------------------------------------
__global__ void pack_kernel(const float* __restrict__ x) {
    int i = blockIdx.x * 256 + threadIdx.x;   // exactly 3,840,000 threads
    int m = i & 1;
    int t = (i >> 1) % 300;
    int r = i / 600;
    int v = r % 25; r /= 25;
    int c = r & 63;
    int n = r >> 6;
    int tok = (((n * 2 + m) * 25 + v) * 300 + t);
    g_xp[tok * 64 + c] = x[i];
}

// ---------------------------------------------------------------------------
// Kernel 2: QKV GEMM  [60000x64] @ [64x768] + b  -> g_qkv  (FFMA2 mainloop)
// ---------------------------------------------------------------------------
__global__ __launch_bounds__(256) void qkv_gemm(const float* __restrict__ w,
                                                const float* __restrict__ bias) {
    __shared__ __align__(16) float As[64][65];
    __shared__ __align__(16) float Bs[64][64];
    int m0 = blockIdx.x * 64;
    int n0 = blockIdx.y * 64;
    int tid = threadIdx.x;
    int tx = tid & 15, ty = tid >> 4;

#pragma unroll
    for (int it = 0; it < 4; ++it) {
        int lin = tid + it * 256;           // float4 index, 0..1023
        int row = lin >> 4;
        int c4  = (lin & 15) * 4;
        float4 f = make_float4(0.f, 0.f, 0.f, 0.f);
        if (m0 + row < NTOK)
            f = *(const float4*)(g_xp + (size_t)(m0 + row) * 64 + c4);
        As[row][c4 + 0] = f.x; As[row][c4 + 1] = f.y;
        As[row][c4 + 2] = f.z; As[row][c4 + 3] = f.w;
        *(float4*)&Bs[row][c4] = *(const float4*)(w + row * QKVW + n0 + c4);
    }
    __syncthreads();

    float4 bb = *(const float4*)(bias + n0 + tx * 4);
    u64 acc[4][2];
#pragma unroll
    for (int i = 0; i < 4; ++i) {
        acc[i][0] = pack2(bb.x, bb.y);
        acc[i][1] = pack2(bb.z, bb.w);
    }
#pragma unroll
    for (int c = 0; c < 64; ++c) {
        u64 p0 = pack2(As[ty * 4 + 0][c], As[ty * 4 + 0][c]);
        u64 p1 = pack2(As[ty * 4 + 1][c], As[ty * 4 + 1][c]);
        u64 p2 = pack2(As[ty * 4 + 2][c], As[ty * 4 + 2][c]);
        u64 p3 = pack2(As[ty * 4 + 3][c], As[ty * 4 + 3][c]);
        ulonglong2 b2 = *(const ulonglong2*)&Bs[c][tx * 4];
        ffma2(acc[0][0], p0, b2.x); ffma2(acc[0][1], p0, b2.y);
        ffma2(acc[1][0], p1, b2.x); ffma2(acc[1][1], p1, b2.y);
        ffma2(acc[2][0], p2, b2.x); ffma2(acc[2][1], p2, b2.y);
        ffma2(acc[3][0], p3, b2.x); ffma2(acc[3][1], p3, b2.y);
    }
#pragma unroll
    for (int i = 0; i < 4; ++i) {
        int row = m0 + ty * 4 + i;
        if (row < NTOK) {
            float2 lo = unpack2(acc[i][0]);
            float2 hi = unpack2(acc[i][1]);
            float4 f = make_float4(lo.x, lo.y, hi.x, hi.y);
            *(float4*)(g_qkv + (size_t)row * QKVW + n0 + tx * 4) = f;
        }
    }
}

// ---------------------------------------------------------------------------
// Kernel 3: scores. S[gl][l][r] = scale*(q_l . k_r) + q_l . bias[l-r+299]
// 64x64 (l x r) tile per block, 128 threads (8 ty x 16 tx), 8x4 microtile.
// ---------------------------------------------------------------------------
__global__ __launch_bounds__(128, 3) void scores_kernel(const float* __restrict__ bias_table,
                                                        int g0) {
    __shared__ __align__(16) float Qs[64][36];
    __shared__ __align__(16) float Ks[64][36];
    __shared__ __align__(16) float Bs[127][36];

    int gl = blockIdx.x;          // 0..GCHUNK-1
    int g  = g0 + gl;
    int bv = g >> 3;
    int h  = g & 7;
    int l0 = blockIdx.y * 64;
    int r0 = blockIdx.z * 64;
    int tid = threadIdx.x;
    const float* qkv_bv = g_qkv + (size_t)bv * (T_ * QKVW);

    // stage Q (linear) and K (pre-scaled, quad-rotated)
    for (int i = tid; i < 512; i += 128) {          // 64 rows x 8 float4
        int row = i >> 3;
        int c = i & 7;                               // chunk index
        int lq = min(l0 + row, T_ - 1);
        int rq = min(r0 + row, T_ - 1);
        float4 qf = *(const float4*)(qkv_bv + (size_t)lq * QKVW + h * 32 + c * 4);
        *(float4*)&Qs[row][c * 4] = qf;
        float4 kf = *(const float4*)(qkv_bv + (size_t)rq * QKVW + 256 + h * 32 + c * 4);
        kf.x *= 0.0625f; kf.y *= 0.0625f; kf.z *= 0.0625f; kf.w *= 0.0625f;
        *(float4*)&Ks[row][((c + (row >> 2)) & 7) * 4] = kf;
    }
    // stage bias band: rows p = pmin..pmin+126 (clamped), quad-rotated
    int pmin = l0 - r0 + 236;
    for (int i = tid; i < 127 * 8; i += 128) {
        int row = i >> 3;
        int c = i & 7;
        int p = min(max(pmin + row, 0), 2 * T_ - 2);
        *(float4*)&Bs[row][((c + (row >> 2)) & 7) * 4] =
            *(const float4*)(bias_table + p * 32 + c * 4);
    }
    __syncthreads();

    int tx = tid & 15, ty = tid >> 4;    // tx: 16 r-groups of 4, ty: 8 l-groups of 8
    u64 acc[8][4];
#pragma unroll
    for (int i = 0; i < 8; ++i)
#pragma unroll
        for (int j = 0; j < 4; ++j) acc[i][j] = 0ull;

    int bbase = 8 * ty - 4 * tx + 60;    // b2[dd] row = bbase + dd, dd in [0,10]

#pragma unroll
    for (int ch = 0; ch < 8; ++ch) {
        ulonglong2 q2[8], k2[4], b2[11];
#pragma unroll
        for (int i = 0; i < 8; ++i)
            q2[i] = *(const ulonglong2*)&Qs[8 * ty + i][ch * 4];
#pragma unroll
        for (int j = 0; j < 4; ++j)
            k2[j] = *(const ulonglong2*)&Ks[4 * tx + j][((ch + tx) & 7) * 4];
#pragma unroll
        for (int dd = 0; dd < 11; ++dd) {
            int bi = bbase + dd;
            b2[dd] = *(const ulonglong2*)&Bs[bi][((ch + (bi >> 2)) & 7) * 4];
        }
#pragma unroll
        for (int i = 0; i < 8; ++i)
#pragma unroll
            for (int j = 0; j < 4; ++j) {
                ulonglong2 bb = b2[i - j + 3];
                ffma2(acc[i][j], q2[i].x, k2[j].x);
                ffma2(acc[i][j], q2[i].y, k2[j].y);
                ffma2(acc[i][j], q2[i].x, bb.x);
                ffma2(acc[i][j], q2[i].y, bb.y);
            }
    }

    // epilogue: horizontal add, store S[gl][l][r] (r contiguous, float4)
    int la = l0 + 8 * ty;
    int ra = r0 + 4 * tx;
#pragma unroll
    for (int i = 0; i < 8; ++i) {
        int l = la + i;
        if (l < T_ && ra < T_) {     // ra % 4 == 0, T_ % 4 == 0 -> full float4 ok
            float4 o = make_float4(hsum2(acc[i][0]), hsum2(acc[i][1]),
                                   hsum2(acc[i][2]), hsum2(acc[i][3]));
            *(float4*)&g_s[((size_t)gl * T_ + l) * T_ + ra] = o;
        }
    }
}

// ---------------------------------------------------------------------------
// Kernel 4: pv_kernel — exp (no max-sub, shift-invariant) + PV GEMM.
// 64 threads, tile 64 l x 32 d, r-chunks of 60. Staging thread t owns
// row l0+t (register ssum). Microtile 8l(4 u64 pairs) x 4d, FMA-bound.
// ---------------------------------------------------------------------------
#define RC 60
#define PL 66

__global__ __launch_bounds__(64) void pv_kernel(int g0) {
    __shared__ __align__(16) float Pt[RC][PL];   // P[r][l], pitch 66
    __shared__ __align__(16) float Vs[RC][32];
    __shared__ float inv_s[64];

    int gl = blockIdx.x;          // 0..GCHUNK-1
    int g  = g0 + gl;
    int bv = g >> 3;
    int h  = g & 7;
    int l0 = blockIdx.y * 64;
    int tid = threadIdx.x;        // 0..63
    int lthr = tid & 7, dthr = tid >> 3;

    const float* qkv_bv = g_qkv + (size_t)bv * (T_ * QKVW);
    const float* Sl = g_s + (size_t)gl * (T_ * T_) + (size_t)(l0 + tid) * T_;
    bool svalid = (l0 + tid) < T_;

    float ssum = 0.f;
    u64 acc[4][4];
#pragma unroll
    for (int i = 0; i < 4; ++i)
#pragma unroll
        for (int j = 0; j < 4; ++j) acc[i][j] = 0ull;

    for (int r0 = 0; r0 < T_; r0 += RC) {
        __syncthreads();
        // stage V chunk: 60 rows x 8 float4 = 480 / 64 threads
        for (int i = tid; i < RC * 8; i += 64) {
            int r = i >> 3, d4 = (i & 7) * 4;
            *(float4*)&Vs[r][d4] =
                *(const float4*)(qkv_bv + (size_t)(r0 + r) * QKVW + 512 + h * 32 + d4);
        }
        // stage P column l = l0+tid: read S row, exp, transpose-store
        if (svalid) {
#pragma unroll
            for (int i4 = 0; i4 < RC / 4; ++i4) {
                float4 s = *(const float4*)(Sl + r0 + i4 * 4);
                float p0 = __expf(s.x), p1 = __expf(s.y);
                float p2 = __expf(s.z), p3 = __expf(s.w);
                ssum += (p0 + p1) + (p2 + p3);
                Pt[i4 * 4 + 0][tid] = p0;
                Pt[i4 * 4 + 1][tid] = p1;
                Pt[i4 * 4 + 2][tid] = p2;
                Pt[i4 * 4 + 3][tid] = p3;
            }
        } else {
#pragma unroll
            for (int r = 0; r < RC; ++r) Pt[r][tid] = 0.f;
        }
        __syncthreads();
        // GEMM: acc[pl][d] += P-pair * v_d
#pragma unroll 4
        for (int r = 0; r < RC; ++r) {
            u64 p2[4];
#pragma unroll
            for (int pl = 0; pl < 4; ++pl)
                p2[pl] = *(const u64*)&Pt[r][16 * pl + 2 * lthr];
            float4 v = *(const float4*)&Vs[r][dthr * 4];
            u64 v0 = pack2(v.x, v.x), v1 = pack2(v.y, v.y);
            u64 v2 = pack2(v.z, v.z), v3 = pack2(v.w, v.w);
#pragma unroll
            for (int pl = 0; pl < 4; ++pl) {
                ffma2(acc[pl][0], p2[pl], v0);
                ffma2(acc[pl][1], p2[pl], v1);
                ffma2(acc[pl][2], p2[pl], v2);
                ffma2(acc[pl][3], p2[pl], v3);
            }
        }
    }

    __syncthreads();
    inv_s[tid] = svalid ? (1.0f / ssum) : 0.f;
    __syncthreads();

#pragma unroll
    for (int pl = 0; pl < 4; ++pl) {
        int ll = 16 * pl + 2 * lthr;     // even l of the pair
        int l = l0 + ll;
        if (l < T_) {
            float iv = inv_s[ll];
            float4 f = make_float4(unpack2(acc[pl][0]).x * iv,
                                   unpack2(acc[pl][1]).x * iv,
                                   unpack2(acc[pl][2]).x * iv,
                                   unpack2(acc[pl][3]).x * iv);
            *(float4*)(g_ao + ((size_t)bv * T_ + l) * E_ + h * 32 + dthr * 4) = f;
        }
        if (l + 1 < T_) {
            float iv = inv_s[ll + 1];
            float4 f = make_float4(unpack2(acc[pl][0]).y * iv,
                                   unpack2(acc[pl][1]).y * iv,
                                   unpack2(acc[pl][2]).y * iv,
                                   unpack2(acc[pl][3]).y * iv);
            *(float4*)(g_ao + ((size_t)bv * T_ + l + 1) * E_ + h * 32 + dthr * 4) = f;
        }
    }
}

// ---------------------------------------------------------------------------
// Kernel 5: merge GEMM [60000x256]@[256x64] + b, scatter (FFMA2 mainloop)
// ---------------------------------------------------------------------------
__global__ __launch_bounds__(256) void merge_gemm(const float* __restrict__ w,
                                                  const float* __restrict__ bias,
                                                  float* __restrict__ out) {
    __shared__ __align__(16) float As[64][65];
    __shared__ __align__(16) float Bs[64][64];
    int m0 = blockIdx.x * 64;
    int tid = threadIdx.x;
    int tx = tid & 15, ty = tid >> 4;

    float4 bb = *(const float4*)(bias + tx * 4);
    u64 acc[4][2];
#pragma unroll
    for (int i = 0; i < 4; ++i) {
        acc[i][0] = pack2(bb.x, bb.y);
        acc[i][1] = pack2(bb.z, bb.w);
    }

    for (int k0 = 0; k0 < 256; k0 += 64) {
        __syncthreads();
#pragma unroll
        for (int it = 0; it < 4; ++it) {
            int lin = tid + it * 256;
            int row = lin >> 4;
            int c4  = (lin & 15) * 4;
            float4 f = make_float4(0.f, 0.f, 0.f, 0.f);
            if (m0 + row < NTOK)
                f = *(const float4*)(g_ao + (size_t)(m0 + row) * E_ + k0 + c4);
            As[row][c4 + 0] = f.x; As[row][c4 + 1] = f.y;
            As[row][c4 + 2] = f.z; As[row][c4 + 3] = f.w;
            *(float4*)&Bs[row][c4] = *(const float4*)(w + (k0 + row) * 64 + c4);
        }
        __syncthreads();
#pragma unroll
        for (int c = 0; c < 64; ++c) {
            u64 p0 = pack2(As[ty * 4 + 0][c], As[ty * 4 + 0][c]);
            u64 p1 = pack2(As[ty * 4 + 1][c], As[ty * 4 + 1][c]);
            u64 p2 = pack2(As[ty * 4 + 2][c], As[ty * 4 + 2][c]);
            u64 p3 = pack2(As[ty * 4 + 3][c], As[ty * 4 + 3][c]);
            ulonglong2 b2 = *(const ulonglong2*)&Bs[c][tx * 4];
            ffma2(acc[0][0], p0, b2.x); ffma2(acc[0][1], p0, b2.y);
            ffma2(acc[1][0], p1, b2.x); ffma2(acc[1][1], p1, b2.y);
            ffma2(acc[2][0], p2, b2.x); ffma2(acc[2][1], p2, b2.y);
            ffma2(acc[3][0], p3, b2.x); ffma2(acc[3][1], p3, b2.y);
        }
    }

#pragma unroll
    for (int i = 0; i < 4; ++i) {
        int tok = m0 + ty * 4 + i;
        if (tok < NTOK) {
            int t  = tok % 300;
            int bvv = tok / 300;
            int v  = bvv % 25;
            int b  = bvv / 25;
            int n  = b >> 1;
            int mm = b & 1;
            size_t base = (size_t)n * 960000 + (size_t)v * 600 + t * 2 + mm;
            float2 lo = unpack2(acc[i][0]);
            float2 hi = unpack2(acc[i][1]);
            float r[4] = {lo.x, lo.y, hi.x, hi.y};
#pragma unroll
            for (int j = 0; j < 4; ++j)
                out[base + (size_t)(tx * 4 + j) * 15000] = r[j];
        }
    }
}

// ---------------------------------------------------------------------------
extern "C" void kernel_launch(void* const* d_in, const int* in_sizes, int n_in,
                              void* d_out, int out_size) {
    const float* x          = (const float*)d_in[0];
    const float* w_qkv      = (const float*)d_in[1];
    const float* b_qkv      = (const float*)d_in[2];
    const float* w_merge    = (const float*)d_in[3];
    const float* b_merge    = (const float*)d_in[4];
    const float* bias_table = (const float*)d_in[5];
    float* out = (float*)d_out;

    pack_kernel<<<15000, 256>>>(x);

    dim3 g1((NTOK + 63) / 64, QKVW / 64);
    qkv_gemm<<<g1, 256>>>(w_qkv, b_qkv);

    for (int c = 0; c < NCHUNK; ++c) {
        dim3 gs(GCHUNK, 5, 5);         // 200 groups x 5 l-tiles x 5 r-tiles
        scores_kernel<<<gs, 128>>>(bias_table, c * GCHUNK);
        dim3 g2(GCHUNK, 5);            // 200 groups x 5 l-tiles of 64
        pv_kernel<<<g2, 64>>>(c * GCHUNK);
    }

    merge_gemm<<<(NTOK + 63) / 64, 256>>>(w_merge, b_merge, out);
}